// round 12
// baseline (speedup 1.0000x reference)
#include <cuda_runtime.h>
#include <cstdint>

#define NN 8
#define TT 64
#define VV 200
#define FF 64
#define FOUT 64
#define NT 512
#define KC 16          // u per chunk in kernelBtc
#define NCH 13         // chunks: 12 full (16u) + 1 partial (8u)

typedef unsigned long long u64;
typedef unsigned int u32;

__device__ __forceinline__ void cpa16(u32 dst, const void* src) {
    asm volatile("cp.async.cg.shared.global [%0], [%1], 16;" :: "r"(dst), "l"(src));
}
#define CP_COMMIT()   asm volatile("cp.async.commit_group;" ::: "memory")
#define CP_WAIT_ALL() asm volatile("cp.async.wait_group 0;" ::: "memory")

// pack two f32 -> bf16x2 (first arg -> LOW half, second -> HIGH half)
__device__ __forceinline__ u32 cvt_bf2(float lo, float hi) {
    u32 r; asm("cvt.rn.bf16x2.f32 %0, %1, %2;" : "=r"(r) : "f"(hi), "f"(lo)); return r;
}

// BF16 mma m16n8k16: D += A*B (fp32 accum, in place)
__device__ __forceinline__ void mma16(float* d, const u32* a, const u32* b) {
    asm volatile(
        "mma.sync.aligned.m16n8k16.row.col.f32.bf16.bf16.f32 "
        "{%0,%1,%2,%3},{%4,%5,%6,%7},{%8,%9},{%0,%1,%2,%3};"
        : "+f"(d[0]), "+f"(d[1]), "+f"(d[2]), "+f"(d[3])
        : "r"(a[0]), "r"(a[1]), "r"(a[2]), "r"(a[3]),
          "r"(b[0]), "r"(b[1]));
}

// scratch (static device globals; no runtime allocation)
__device__ __align__(16) float g_y0[(size_t)NT*VV*FOUT];
__device__ __align__(16) float g_y1[(size_t)NT*VV*FOUT];
__device__ __align__(16) float g_y2[(size_t)NT*VV*FOUT];

// ---------------------------------------------------------------------------
// kernelGtc: y_k = x @ Theta_k via bf16 mma, 3-term hi/lo split (~1e-5 acc).
// grid (3, NT), 416 threads (13 warps), warp w owns v rows [16w, 16w+16).
// ---------------------------------------------------------------------------
#define GQ 73    // uint2 row stride for packed Theta

__global__ void __launch_bounds__(416) kernelGtc(
        const float* __restrict__ x,
        const float* __restrict__ Theta) {
    extern __shared__ __align__(16) uint2 sgt[];
    uint2* thH2 = sgt;               // 16 * GQ
    uint2* thL2 = sgt + 16 * GQ;     // 16 * GQ

    int k  = blockIdx.x;
    int nt = blockIdx.y;
    int tid = threadIdx.x;
    int w = tid >> 5, lane = tid & 31;
    int g = lane >> 2, tg = lane & 3;
    int vbase = w * 16;

    const float* Tk = Theta + (size_t)k * FF * FOUT;
    for (int idx = tid; idx < 2048; idx += 416) {
        int f2 = idx >> 6, fo = idx & 63;
        float t0 = Tk[(2 * f2) * 64 + fo];
        float t1 = Tk[(2 * f2 + 1) * 64 + fo];
        u32 h = cvt_bf2(t0, t1);
        float h0 = __uint_as_float(h << 16);
        float h1 = __uint_as_float(h & 0xffff0000u);
        u32 l = cvt_bf2(t0 - h0, t1 - h1);
        int ks = f2 >> 3, tgx = f2 & 7;
        int q = 4 * ks + (tgx & 3);
        if (tgx < 4) { thH2[q * GQ + fo].x = h; thL2[q * GQ + fo].x = l; }
        else         { thH2[q * GQ + fo].y = h; thL2[q * GQ + fo].y = l; }
    }
    __syncthreads();

    const float* xnt = x + (size_t)nt * VV * FF;
    int r0 = vbase + g;
    int r1 = r0 + 8;
    bool ok1 = (r1 < VV);
    float2 xr[4][4];
#pragma unroll
    for (int ks = 0; ks < 4; ++ks) {
        int f = 16 * ks + 2 * tg;
        xr[ks][0] = *(const float2*)(xnt + (size_t)r0 * FF + f);
        xr[ks][2] = *(const float2*)(xnt + (size_t)r0 * FF + f + 8);
        if (ok1) {
            xr[ks][1] = *(const float2*)(xnt + (size_t)r1 * FF + f);
            xr[ks][3] = *(const float2*)(xnt + (size_t)r1 * FF + f + 8);
        } else {
            xr[ks][1] = make_float2(0.f, 0.f);
            xr[ks][3] = make_float2(0.f, 0.f);
        }
    }

    float acc[8][4];
#pragma unroll
    for (int nn = 0; nn < 8; ++nn)
#pragma unroll
        for (int j = 0; j < 4; ++j) acc[nn][j] = 0.f;

#pragma unroll
    for (int ks = 0; ks < 4; ++ks) {
        u32 Ah[4], Al[4];
#pragma unroll
        for (int s = 0; s < 4; ++s) {
            float a0 = xr[ks][s].x, a1 = xr[ks][s].y;
            u32 h = cvt_bf2(a0, a1);
            float h0 = __uint_as_float(h << 16);
            float h1 = __uint_as_float(h & 0xffff0000u);
            Ah[s] = h;
            Al[s] = cvt_bf2(a0 - h0, a1 - h1);
        }
        int fbq = (4 * ks + tg) * GQ;
#pragma unroll
        for (int nn = 0; nn < 8; ++nn) {
            int fo = 8 * nn + g;
            uint2 BhP = thH2[fbq + fo];
            uint2 BlP = thL2[fbq + fo];
            u32 Bh[2] = { BhP.x, BhP.y };
            u32 Bl[2] = { BlP.x, BlP.y };
            mma16(acc[nn], Ah, Bh);
            mma16(acc[nn], Ah, Bl);
            mma16(acc[nn], Al, Bh);
        }
    }

    float* yk = (k == 0 ? g_y0 : (k == 1 ? g_y1 : g_y2)) + (size_t)nt * VV * FOUT;
#pragma unroll
    for (int nn = 0; nn < 8; ++nn) {
        int c = 8 * nn + 2 * tg;
        *(float2*)(yk + (size_t)r0 * FOUT + c) = make_float2(acc[nn][0], acc[nn][1]);
        if (ok1)
            *(float2*)(yk + (size_t)r1 * FOUT + c) = make_float2(acc[nn][2], acc[nn][3]);
    }
}

// ---------------------------------------------------------------------------
// kernelBtc v2: 416 threads (13 warps), warp w owns v in [16w, 16w+16).
//   S/Att/S-col single-buffered (read only in frag-gen phase);
//   Y double-buffered (read in MMA phase while next chunk stages).
//   Fast frag-gen path (no predicates) except diag / partial / v-tail warps.
// ---------------------------------------------------------------------------
#define SRS 228                 // s_row / att row stride (floats)
#define SCT 20                  // s_col row stride (floats)
#define SMY 68                  // y row stride (floats)
#define BUF_SR (KC * SRS)       // 3648
#define BUF_SC (VV * SCT)       // 4000
#define BUF_Y  (KC * SMY)       // 1088
#define OFF_SR 0
#define OFF_SA BUF_SR                        // 3648
#define OFF_SC (2 * BUF_SR)                  // 7296
#define OFF_Y1 (2 * BUF_SR + BUF_SC)         // 11296
#define OFF_Y2 (OFF_Y1 + 2 * BUF_Y)          // 13472
#define SMB_FLOATS (OFF_Y2 + 2 * BUF_Y)      // 15648 fl = 62592 B

__global__ void __launch_bounds__(416, 2) kernelBtc(const float* __restrict__ S,
                                                    const float* __restrict__ Att,
                                                    float* __restrict__ out) {
    extern __shared__ __align__(16) float sm[];
    int nt = blockIdx.x;
    int n  = nt / TT;
    int tid = threadIdx.x;
    int w = tid >> 5, lane = tid & 31;
    int g = lane >> 2, tg = lane & 3;
    int vbase = w * 16;

    const float* Snt = S + (size_t)nt * VV * VV;
    const float* Atn = Att + (size_t)n * VV * VV;
    const float* y0g = g_y0 + (size_t)nt * VV * FOUT;
    const float* y1g = g_y1 + (size_t)nt * VV * FOUT;
    const float* y2g = g_y2 + (size_t)nt * VV * FOUT;

    float acc[8][4];
#pragma unroll
    for (int nn = 0; nn < 8; ++nn)
#pragma unroll
        for (int j = 0; j < 4; ++j) acc[nn][j] = 0.f;
    float dacc[2] = {0.f, 0.f};

    auto stage = [&](int c) {
        int u0 = c * KC;
        int uw = (c == NCH - 1) ? 8 : KC;
        int b = c & 1;
        for (int i = tid; i < uw * 50; i += 416) {
            int r = i / 50, s = i - r * 50;
            cpa16((u32)__cvta_generic_to_shared(sm + OFF_SR + r * SRS + s * 4),
                  Snt + (size_t)(u0 + r) * VV + s * 4);
            cpa16((u32)__cvta_generic_to_shared(sm + OFF_SA + r * SRS + s * 4),
                  Atn + (size_t)(u0 + r) * VV + s * 4);
        }
        int cps = uw / 4;
        for (int i = tid; i < VV * cps; i += 416) {
            int r = i / cps, s = i - r * cps;
            cpa16((u32)__cvta_generic_to_shared(sm + OFF_SC + r * SCT + s * 4),
                  Snt + (size_t)r * VV + u0 + s * 4);
        }
        for (int i = tid; i < uw * 16; i += 416) {
            int r = i >> 4, s = i & 15;
            cpa16((u32)__cvta_generic_to_shared(sm + OFF_Y1 + b * BUF_Y + r * SMY + s * 4),
                  y1g + (size_t)(u0 + r) * FOUT + s * 4);
            cpa16((u32)__cvta_generic_to_shared(sm + OFF_Y2 + b * BUF_Y + r * SMY + s * 4),
                  y2g + (size_t)(u0 + r) * FOUT + s * 4);
        }
        CP_COMMIT();
    };

    stage(0);

    int uA = 2 * tg, uC = 2 * tg + 8;
    int vA = vbase + g, vB = vA + 8;
    bool vtail = (vbase + 15 >= VV);     // only warp 12

    for (int c = 0; c < NCH; ++c) {
        int b = c & 1;
        int u0 = c * KC;
        CP_WAIT_ALL();
        __syncthreads();

        const float* sr = sm + OFF_SR;
        const float* sa = sm + OFF_SA;
        const float* sc = sm + OFF_SC;

        // ---- A fragments ----
        u32 af1[4], af2[4];
        {
            float c1v[2][4], c2v[2][4];
            bool fast = (u0 != vbase) && (c != NCH - 1) && !vtail;
            if (fast) {
#pragma unroll
                for (int s = 0; s < 4; ++s) {
                    int ul = (s < 2) ? (uA + s) : (uC + s - 2);
                    float mA = fminf(sr[ul * SRS + vA], sc[vA * SCT + ul]);
                    float mB = fminf(sr[ul * SRS + vB], sc[vB * SCT + ul]);
                    float aA = sa[ul * SRS + vA];
                    float aB = sa[ul * SRS + vB];
                    dacc[0] += mA; dacc[1] += mB;
                    float p1A = -mA * aA, p1B = -mB * aB;
                    c1v[0][s] = p1A;  c2v[0][s] = -2.f * mA * p1A;
                    c1v[1][s] = p1B;  c2v[1][s] = -2.f * mB * p1B;
                }
            } else {
#pragma unroll
                for (int s = 0; s < 4; ++s) {
                    int ul = (s < 2) ? (uA + s) : (uC + s - 2);
                    int ugl = u0 + ul;
                    float mA = fminf(sr[ul * SRS + vA], sc[vA * SCT + ul]);
                    float mB = fminf(sr[ul * SRS + vB], sc[vB * SCT + ul]);
                    float aA = sa[ul * SRS + vA];
                    float aB = sa[ul * SRS + vB];
                    bool uok = (ugl < VV);
                    if (uok) { dacc[0] += mA; dacc[1] += mB; }
                    bool okA = uok && (vA < VV) && (ugl != vA);
                    bool okB = uok && (vB < VV) && (ugl != vB);
                    float p1A = -mA * aA, p1B = -mB * aB;
                    c1v[0][s] = okA ? p1A : 0.f;  c2v[0][s] = okA ? -2.f * mA * p1A : 0.f;
                    c1v[1][s] = okB ? p1B : 0.f;  c2v[1][s] = okB ? -2.f * mB * p1B : 0.f;
                }
            }
            af1[0] = cvt_bf2(c1v[0][0], c1v[0][1]);
            af1[1] = cvt_bf2(c1v[1][0], c1v[1][1]);
            af1[2] = cvt_bf2(c1v[0][2], c1v[0][3]);
            af1[3] = cvt_bf2(c1v[1][2], c1v[1][3]);
            af2[0] = cvt_bf2(c2v[0][0], c2v[0][1]);
            af2[1] = cvt_bf2(c2v[1][0], c2v[1][1]);
            af2[2] = cvt_bf2(c2v[0][2], c2v[0][3]);
            af2[3] = cvt_bf2(c2v[1][2], c2v[1][3]);
        }
        __syncthreads();                 // S bufs free; Y[b] still in use below

        if (c + 1 < NCH) stage(c + 1);   // overwrites S bufs + Y[b^1]

        // ---- MMA phase: transient B-frags from Y[b] ----
        const float* y1b = sm + OFF_Y1 + b * BUF_Y;
        const float* y2b = sm + OFF_Y2 + b * BUF_Y;
#pragma unroll
        for (int nn = 0; nn < 8; ++nn) {
            int fo = 8 * nn + g;
            u32 b1[2], b2[2];
            b1[0] = cvt_bf2(y1b[uA * SMY + fo], y1b[(uA + 1) * SMY + fo]);
            b1[1] = cvt_bf2(y1b[uC * SMY + fo], y1b[(uC + 1) * SMY + fo]);
            b2[0] = cvt_bf2(y2b[uA * SMY + fo], y2b[(uA + 1) * SMY + fo]);
            b2[1] = cvt_bf2(y2b[uC * SMY + fo], y2b[(uC + 1) * SMY + fo]);
            mma16(acc[nn], af1, b1);
            mma16(acc[nn], af2, b2);
        }
    }

    // ---- reduce d over tg lanes ----
    float dred[2];
#pragma unroll
    for (int h = 0; h < 2; ++h) {
        float dv = dacc[h];
        dv += __shfl_xor_sync(0xffffffffu, dv, 1);
        dv += __shfl_xor_sync(0xffffffffu, dv, 2);
        dred[h] = dv;
    }

    // ---- epilogue: exact fp32 diagonal base + off-diag acc, relu ----
#pragma unroll
    for (int h = 0; h < 2; ++h) {
        int v = vbase + g + 8 * h;
        if (v < VV) {
            float avv = Atn[(size_t)v * VV + v];
            float svv = Snt[(size_t)v * VV + v];
            float l = dred[h] - 1.0f - svv;
            float c1d = l * avv;
            float c2d = (2.0f * l * l - 1.0f) * avv;
            const float* y0r = y0g + (size_t)v * FOUT;
            const float* y1r = y1g + (size_t)v * FOUT;
            const float* y2r = y2g + (size_t)v * FOUT;
            float* orow = out + ((size_t)nt * VV + v) * FOUT;
#pragma unroll
            for (int nn = 0; nn < 8; ++nn) {
                int fo = 8 * nn + 2 * tg;
                float2 p0 = *(const float2*)(y0r + fo);
                float2 p1 = *(const float2*)(y1r + fo);
                float2 p2 = *(const float2*)(y2r + fo);
                float2 o;
                o.x = fmaxf(avv * p0.x + c1d * p1.x + c2d * p2.x
                            + acc[nn][2 * h + 0], 0.f);
                o.y = fmaxf(avv * p0.y + c1d * p1.y + c2d * p2.y
                            + acc[nn][2 * h + 1], 0.f);
                *(float2*)(orow + fo) = o;
            }
        }
    }
}

// ---------------------------------------------------------------------------
extern "C" void kernel_launch(void* const* d_in, const int* in_sizes, int n_in,
                              void* d_out, int out_size) {
    (void)in_sizes; (void)n_in; (void)out_size;
    const float* x     = (const float*)d_in[0];
    const float* Att   = (const float*)d_in[1];
    const float* S     = (const float*)d_in[2];
    const float* Theta = (const float*)d_in[3];
    float* out = (float*)d_out;

    const int smemG = 32 * GQ * 8;        // 18688
    const int smemB = SMB_FLOATS * 4;     // 62592
    cudaFuncSetAttribute(kernelGtc, cudaFuncAttributeMaxDynamicSharedMemorySize, smemG);
    cudaFuncSetAttribute(kernelBtc, cudaFuncAttributeMaxDynamicSharedMemorySize, smemB);

    kernelGtc<<<dim3(3, NT), 416, smemG>>>(x, Theta);
    kernelBtc<<<NT, 416, smemB>>>(S, Att, out);
}

// round 13
// speedup vs baseline: 1.0154x; 1.0154x over previous
#include <cuda_runtime.h>
#include <cstdint>

#define NN 8
#define TT 64
#define VV 200
#define FF 64
#define FOUT 64
#define NT 512
#define KC 16          // u per chunk in kernelBtc
#define NCH 13         // chunks: 12 full (16u) + 1 partial (8u)

typedef unsigned long long u64;
typedef unsigned int u32;

__device__ __forceinline__ void cpa16(u32 dst, const void* src) {
    asm volatile("cp.async.cg.shared.global [%0], [%1], 16;" :: "r"(dst), "l"(src));
}
#define CP_COMMIT()   asm volatile("cp.async.commit_group;" ::: "memory")
#define CP_WAIT_ALL() asm volatile("cp.async.wait_group 0;" ::: "memory")

// pack two f32 -> bf16x2 (first arg -> LOW half, second -> HIGH half)
__device__ __forceinline__ u32 cvt_bf2(float lo, float hi) {
    u32 r; asm("cvt.rn.bf16x2.f32 %0, %1, %2;" : "=r"(r) : "f"(hi), "f"(lo)); return r;
}

// BF16 mma m16n8k16: D += A*B (fp32 accum, in place)
__device__ __forceinline__ void mma16(float* d, const u32* a, const u32* b) {
    asm volatile(
        "mma.sync.aligned.m16n8k16.row.col.f32.bf16.bf16.f32 "
        "{%0,%1,%2,%3},{%4,%5,%6,%7},{%8,%9},{%0,%1,%2,%3};"
        : "+f"(d[0]), "+f"(d[1]), "+f"(d[2]), "+f"(d[3])
        : "r"(a[0]), "r"(a[1]), "r"(a[2]), "r"(a[3]),
          "r"(b[0]), "r"(b[1]));
}

// scratch (static device globals; no runtime allocation)
__device__ __align__(16) float g_y0[(size_t)NT*VV*FOUT];
__device__ __align__(16) float g_y1[(size_t)NT*VV*FOUT];
__device__ __align__(16) float g_y2[(size_t)NT*VV*FOUT];
__device__ __align__(16) u32   g_y1p[(size_t)NT*100*FOUT];  // bf16x2 (u,u+1) pairs
__device__ __align__(16) u32   g_y2p[(size_t)NT*100*FOUT];

// ---------------------------------------------------------------------------
// kernelGtc: y_k = x @ Theta_k via bf16 mma, 3-term hi/lo split (~1e-5 acc).
// Also emits bf16x2-packed y1p/y2p in MMA-B-fragment layout (pairs along u).
// grid (3, NT), 416 threads (13 warps), warp w owns v rows [16w, 16w+16).
// ---------------------------------------------------------------------------
#define GQ 73    // uint2 row stride for packed Theta

__global__ void __launch_bounds__(416) kernelGtc(
        const float* __restrict__ x,
        const float* __restrict__ Theta) {
    extern __shared__ __align__(16) uint2 sgt[];
    uint2* thH2 = sgt;               // 16 * GQ
    uint2* thL2 = sgt + 16 * GQ;     // 16 * GQ

    int k  = blockIdx.x;
    int nt = blockIdx.y;
    int tid = threadIdx.x;
    int w = tid >> 5, lane = tid & 31;
    int g = lane >> 2, tg = lane & 3;
    int vbase = w * 16;

    const float* Tk = Theta + (size_t)k * FF * FOUT;
    for (int idx = tid; idx < 2048; idx += 416) {
        int f2 = idx >> 6, fo = idx & 63;
        float t0 = Tk[(2 * f2) * 64 + fo];
        float t1 = Tk[(2 * f2 + 1) * 64 + fo];
        u32 h = cvt_bf2(t0, t1);
        float h0 = __uint_as_float(h << 16);
        float h1 = __uint_as_float(h & 0xffff0000u);
        u32 l = cvt_bf2(t0 - h0, t1 - h1);
        int ks = f2 >> 3, tgx = f2 & 7;
        int q = 4 * ks + (tgx & 3);
        if (tgx < 4) { thH2[q * GQ + fo].x = h; thL2[q * GQ + fo].x = l; }
        else         { thH2[q * GQ + fo].y = h; thL2[q * GQ + fo].y = l; }
    }
    __syncthreads();

    const float* xnt = x + (size_t)nt * VV * FF;
    int r0 = vbase + g;
    int r1 = r0 + 8;
    bool ok1 = (r1 < VV);
    float2 xr[4][4];
#pragma unroll
    for (int ks = 0; ks < 4; ++ks) {
        int f = 16 * ks + 2 * tg;
        xr[ks][0] = *(const float2*)(xnt + (size_t)r0 * FF + f);
        xr[ks][2] = *(const float2*)(xnt + (size_t)r0 * FF + f + 8);
        if (ok1) {
            xr[ks][1] = *(const float2*)(xnt + (size_t)r1 * FF + f);
            xr[ks][3] = *(const float2*)(xnt + (size_t)r1 * FF + f + 8);
        } else {
            xr[ks][1] = make_float2(0.f, 0.f);
            xr[ks][3] = make_float2(0.f, 0.f);
        }
    }

    float acc[8][4];
#pragma unroll
    for (int nn = 0; nn < 8; ++nn)
#pragma unroll
        for (int j = 0; j < 4; ++j) acc[nn][j] = 0.f;

#pragma unroll
    for (int ks = 0; ks < 4; ++ks) {
        u32 Ah[4], Al[4];
#pragma unroll
        for (int s = 0; s < 4; ++s) {
            float a0 = xr[ks][s].x, a1 = xr[ks][s].y;
            u32 h = cvt_bf2(a0, a1);
            float h0 = __uint_as_float(h << 16);
            float h1 = __uint_as_float(h & 0xffff0000u);
            Ah[s] = h;
            Al[s] = cvt_bf2(a0 - h0, a1 - h1);
        }
        int fbq = (4 * ks + tg) * GQ;
#pragma unroll
        for (int nn = 0; nn < 8; ++nn) {
            int fo = 8 * nn + g;
            uint2 BhP = thH2[fbq + fo];
            uint2 BlP = thL2[fbq + fo];
            u32 Bh[2] = { BhP.x, BhP.y };
            u32 Bl[2] = { BlP.x, BlP.y };
            mma16(acc[nn], Ah, Bh);
            mma16(acc[nn], Ah, Bl);
            mma16(acc[nn], Al, Bh);
        }
    }

    // fp32 stores (epilogue needs exact y for the diagonal term)
    float* yk = (k == 0 ? g_y0 : (k == 1 ? g_y1 : g_y2)) + (size_t)nt * VV * FOUT;
#pragma unroll
    for (int nn = 0; nn < 8; ++nn) {
        int c = 8 * nn + 2 * tg;
        *(float2*)(yk + (size_t)r0 * FOUT + c) = make_float2(acc[nn][0], acc[nn][1]);
        if (ok1)
            *(float2*)(yk + (size_t)r1 * FOUT + c) = make_float2(acc[nn][2], acc[nn][3]);
    }

    // bf16x2 packed stores for k=1,2: pair (u even, u odd) along u via shfl
    if (k != 0) {
        u32* ypk = (k == 1 ? g_y1p : g_y2p) + (size_t)nt * 100 * FOUT;
#pragma unroll
        for (int nn = 0; nn < 8; ++nn) {
            float s0 = __shfl_down_sync(0xffffffffu, acc[nn][0], 4);
            float s1 = __shfl_down_sync(0xffffffffu, acc[nn][1], 4);
            float s2 = __shfl_down_sync(0xffffffffu, acc[nn][2], 4);
            float s3 = __shfl_down_sync(0xffffffffu, acc[nn][3], 4);
            if (!(g & 1)) {
                int c = 8 * nn + 2 * tg;
                int u2a = r0 >> 1;            // rows (r0, r0+1)
                *(uint2*)(ypk + (size_t)u2a * FOUT + c) =
                    make_uint2(cvt_bf2(acc[nn][0], s0), cvt_bf2(acc[nn][1], s1));
                if (ok1)                      // rows (r1, r1+1)
                    *(uint2*)(ypk + (size_t)(u2a + 4) * FOUT + c) =
                        make_uint2(cvt_bf2(acc[nn][2], s2), cvt_bf2(acc[nn][3], s3));
            }
        }
    }
}

// ---------------------------------------------------------------------------
// kernelBtc v3: 416 threads (13 warps), warp w owns v in [16w, 16w+16).
//   S/Att/S-col single-buffered (frag-gen phase only);
//   y1p/y2p (bf16x2 pre-packed) double-buffered; MMA phase = 4 LDS + 2 HMMA/nn.
// ---------------------------------------------------------------------------
#define SRS 228                 // s_row / att row stride (floats)
#define SCT 20                  // s_col row stride (floats)
#define SYP 72                  // yp row stride (u32)
#define BUF_SR (KC * SRS)       // 3648
#define BUF_SC (VV * SCT)       // 4000
#define BUF_YP (8 * SYP)        // 576 (u32)
#define OFF_SR 0
#define OFF_SA BUF_SR                        // 3648
#define OFF_SC (2 * BUF_SR)                  // 7296
#define OFF_YP1 (2 * BUF_SR + BUF_SC)        // 11296
#define OFF_YP2 (OFF_YP1 + 2 * BUF_YP)       // 12448
#define SMB_WORDS (OFF_YP2 + 2 * BUF_YP)     // 13600 words = 54400 B

__global__ void __launch_bounds__(416, 2) kernelBtc(const float* __restrict__ S,
                                                    const float* __restrict__ Att,
                                                    float* __restrict__ out) {
    extern __shared__ __align__(16) float sm[];
    int nt = blockIdx.x;
    int n  = nt / TT;
    int tid = threadIdx.x;
    int w = tid >> 5, lane = tid & 31;
    int g = lane >> 2, tg = lane & 3;
    int vbase = w * 16;

    const float* Snt = S + (size_t)nt * VV * VV;
    const float* Atn = Att + (size_t)n * VV * VV;
    const float* y0g = g_y0 + (size_t)nt * VV * FOUT;
    const float* y1g = g_y1 + (size_t)nt * VV * FOUT;
    const float* y2g = g_y2 + (size_t)nt * VV * FOUT;
    const u32* y1pg = g_y1p + (size_t)nt * 100 * FOUT;
    const u32* y2pg = g_y2p + (size_t)nt * 100 * FOUT;

    float acc[8][4];
#pragma unroll
    for (int nn = 0; nn < 8; ++nn)
#pragma unroll
        for (int j = 0; j < 4; ++j) acc[nn][j] = 0.f;
    float dacc[2] = {0.f, 0.f};

    auto stage = [&](int c) {
        int u0 = c * KC;
        int uw = (c == NCH - 1) ? 8 : KC;
        int b = c & 1;
        for (int i = tid; i < uw * 50; i += 416) {
            int r = i / 50, s = i - r * 50;
            cpa16((u32)__cvta_generic_to_shared(sm + OFF_SR + r * SRS + s * 4),
                  Snt + (size_t)(u0 + r) * VV + s * 4);
            cpa16((u32)__cvta_generic_to_shared(sm + OFF_SA + r * SRS + s * 4),
                  Atn + (size_t)(u0 + r) * VV + s * 4);
        }
        int cps = uw / 4;
        for (int i = tid; i < VV * cps; i += 416) {
            int r = i / cps, s = i - r * cps;
            cpa16((u32)__cvta_generic_to_shared(sm + OFF_SC + r * SCT + s * 4),
                  Snt + (size_t)r * VV + u0 + s * 4);
        }
        // packed y tiles: u2 rows [8c, 8c+uw/2), 64 u32 per row
        int yrows = uw / 2;
        u32* sy1 = (u32*)sm + OFF_YP1 + b * BUF_YP;
        u32* sy2 = (u32*)sm + OFF_YP2 + b * BUF_YP;
        for (int i = tid; i < yrows * 16; i += 416) {
            int r = i >> 4, s = i & 15;
            cpa16((u32)__cvta_generic_to_shared(sy1 + r * SYP + s * 4),
                  y1pg + (size_t)(8 * c + r) * FOUT + s * 4);
            cpa16((u32)__cvta_generic_to_shared(sy2 + r * SYP + s * 4),
                  y2pg + (size_t)(8 * c + r) * FOUT + s * 4);
        }
        CP_COMMIT();
    };

    stage(0);

    int uA = 2 * tg, uC = 2 * tg + 8;
    int vA = vbase + g, vB = vA + 8;
    bool vtail = (vbase + 15 >= VV);     // only warp 12

    for (int c = 0; c < NCH; ++c) {
        int b = c & 1;
        int u0 = c * KC;
        CP_WAIT_ALL();
        __syncthreads();

        const float* sr = sm + OFF_SR;
        const float* sa = sm + OFF_SA;
        const float* sc = sm + OFF_SC;

        // ---- A fragments ----
        u32 af1[4], af2[4];
        {
            float c1v[2][4], c2v[2][4];
            bool fast = (u0 != vbase) && (c != NCH - 1) && !vtail;
            if (fast) {
#pragma unroll
                for (int s = 0; s < 4; ++s) {
                    int ul = (s < 2) ? (uA + s) : (uC + s - 2);
                    float mA = fminf(sr[ul * SRS + vA], sc[vA * SCT + ul]);
                    float mB = fminf(sr[ul * SRS + vB], sc[vB * SCT + ul]);
                    float aA = sa[ul * SRS + vA];
                    float aB = sa[ul * SRS + vB];
                    dacc[0] += mA; dacc[1] += mB;
                    float p1A = -mA * aA, p1B = -mB * aB;
                    c1v[0][s] = p1A;  c2v[0][s] = -2.f * mA * p1A;
                    c1v[1][s] = p1B;  c2v[1][s] = -2.f * mB * p1B;
                }
            } else {
#pragma unroll
                for (int s = 0; s < 4; ++s) {
                    int ul = (s < 2) ? (uA + s) : (uC + s - 2);
                    int ugl = u0 + ul;
                    float mA = fminf(sr[ul * SRS + vA], sc[vA * SCT + ul]);
                    float mB = fminf(sr[ul * SRS + vB], sc[vB * SCT + ul]);
                    float aA = sa[ul * SRS + vA];
                    float aB = sa[ul * SRS + vB];
                    bool uok = (ugl < VV);
                    if (uok) { dacc[0] += mA; dacc[1] += mB; }
                    bool okA = uok && (vA < VV) && (ugl != vA);
                    bool okB = uok && (vB < VV) && (ugl != vB);
                    float p1A = -mA * aA, p1B = -mB * aB;
                    c1v[0][s] = okA ? p1A : 0.f;  c2v[0][s] = okA ? -2.f * mA * p1A : 0.f;
                    c1v[1][s] = okB ? p1B : 0.f;  c2v[1][s] = okB ? -2.f * mB * p1B : 0.f;
                }
            }
            af1[0] = cvt_bf2(c1v[0][0], c1v[0][1]);
            af1[1] = cvt_bf2(c1v[1][0], c1v[1][1]);
            af1[2] = cvt_bf2(c1v[0][2], c1v[0][3]);
            af1[3] = cvt_bf2(c1v[1][2], c1v[1][3]);
            af2[0] = cvt_bf2(c2v[0][0], c2v[0][1]);
            af2[1] = cvt_bf2(c2v[1][0], c2v[1][1]);
            af2[2] = cvt_bf2(c2v[0][2], c2v[0][3]);
            af2[3] = cvt_bf2(c2v[1][2], c2v[1][3]);
        }
        __syncthreads();                 // S bufs free; yp[b] still in use below

        if (c + 1 < NCH) stage(c + 1);   // overwrites S bufs + yp[b^1]

        // ---- MMA phase: pre-packed B-frags from yp[b] ----
        const u32* sy1 = (const u32*)sm + OFF_YP1 + b * BUF_YP;
        const u32* sy2 = (const u32*)sm + OFF_YP2 + b * BUF_YP;
#pragma unroll
        for (int nn = 0; nn < 8; ++nn) {
            int fo = 8 * nn + g;
            u32 b1[2] = { sy1[tg * SYP + fo], sy1[(tg + 4) * SYP + fo] };
            u32 b2[2] = { sy2[tg * SYP + fo], sy2[(tg + 4) * SYP + fo] };
            mma16(acc[nn], af1, b1);
            mma16(acc[nn], af2, b2);
        }
    }

    // ---- reduce d over tg lanes ----
    float dred[2];
#pragma unroll
    for (int h = 0; h < 2; ++h) {
        float dv = dacc[h];
        dv += __shfl_xor_sync(0xffffffffu, dv, 1);
        dv += __shfl_xor_sync(0xffffffffu, dv, 2);
        dred[h] = dv;
    }

    // ---- epilogue: exact fp32 diagonal base + off-diag acc, relu ----
#pragma unroll
    for (int h = 0; h < 2; ++h) {
        int v = vbase + g + 8 * h;
        if (v < VV) {
            float avv = Atn[(size_t)v * VV + v];
            float svv = Snt[(size_t)v * VV + v];
            float l = dred[h] - 1.0f - svv;
            float c1d = l * avv;
            float c2d = (2.0f * l * l - 1.0f) * avv;
            const float* y0r = y0g + (size_t)v * FOUT;
            const float* y1r = y1g + (size_t)v * FOUT;
            const float* y2r = y2g + (size_t)v * FOUT;
            float* orow = out + ((size_t)nt * VV + v) * FOUT;
#pragma unroll
            for (int nn = 0; nn < 8; ++nn) {
                int fo = 8 * nn + 2 * tg;
                float2 p0 = *(const float2*)(y0r + fo);
                float2 p1 = *(const float2*)(y1r + fo);
                float2 p2 = *(const float2*)(y2r + fo);
                float2 o;
                o.x = fmaxf(avv * p0.x + c1d * p1.x + c2d * p2.x
                            + acc[nn][2 * h + 0], 0.f);
                o.y = fmaxf(avv * p0.y + c1d * p1.y + c2d * p2.y
                            + acc[nn][2 * h + 1], 0.f);
                *(float2*)(orow + fo) = o;
            }
        }
    }
}

// ---------------------------------------------------------------------------
extern "C" void kernel_launch(void* const* d_in, const int* in_sizes, int n_in,
                              void* d_out, int out_size) {
    (void)in_sizes; (void)n_in; (void)out_size;
    const float* x     = (const float*)d_in[0];
    const float* Att   = (const float*)d_in[1];
    const float* S     = (const float*)d_in[2];
    const float* Theta = (const float*)d_in[3];
    float* out = (float*)d_out;

    const int smemG = 32 * GQ * 8;        // 18688
    const int smemB = SMB_WORDS * 4;      // 54400
    cudaFuncSetAttribute(kernelGtc, cudaFuncAttributeMaxDynamicSharedMemorySize, smemG);
    cudaFuncSetAttribute(kernelBtc, cudaFuncAttributeMaxDynamicSharedMemorySize, smemB);

    kernelGtc<<<dim3(3, NT), 416, smemG>>>(x, Theta);
    kernelBtc<<<NT, 416, smemB>>>(S, Att, out);
}